// round 9
// baseline (speedup 1.0000x reference)
#include <cuda_runtime.h>

// Fixed problem shape (from setup_inputs): B=32, N=64, L=128, D=256
#define B_      32
#define N_      64
#define L_      128
#define D_      256
#define NB_     (B_ * N_)     // 2048
#define MAXLEN_ (N_ * L_)     // 8192

#define ROWS_PER_BLK 32
#define BLKS_PER_B   (MAXLEN_ / ROWS_PER_BLK)   // 256
#define GRID_        (B_ * BLKS_PER_B)          // 8192

// Output layout (flat concat of the reference tuple, fp32):
//   src_out      [MAXLEN, B, 1]
//   mb_out       [MAXLEN, B, D]
//   hidden       [1, B, D]
//   lengths_out  [B]
#define OFF_MB      ((size_t)MAXLEN_ * B_)
#define OFF_HID     (OFF_MB + (size_t)MAXLEN_ * B_ * D_)
#define OFF_LEN     (OFF_HID + (size_t)B_ * D_)

// Mean-pool accumulators + arrival counters. Zero at module load; the last
// block per batch row restores them to zero after use, so every graph
// replay sees identical initial state.
__device__ float g_hid[B_ * D_];
__device__ int   g_cnt[B_];

// ---------------------------------------------------------------------------
// Uniform-gather kernel. Block (b, cb) handles the 32 CONSECUTIVE output
// rows t in [cb*32, cb*32+32) of batch row b — exactly 32 KB of writes and
// <=32 KB of reads per block (perfect balance). Valid rows (t < ltot) map
// to (node, pos) via a 6-step bisection of the per-row length prefix;
// contiguous t keeps the same read-locality class as the scatter version.
// Invalid rows write zeros (mb) / ones (src). Mean-pool partials atomicAdd
// into g_hid; the last-arriving block per batch row finalizes hidden.
// ---------------------------------------------------------------------------
__global__ void __launch_bounds__(256) fused_kernel(
        const float* __restrict__ src,
        const float4* __restrict__ mb,
        const int* __restrict__ lengths,
        const int* __restrict__ recover,
        float* __restrict__ out) {
    __shared__ int sh_off[N_ + 1];     // exclusive prefix; sh_off[64] = ltot
    __shared__ int sh_map[ROWS_PER_BLK];
    __shared__ float4 sh[256];
    __shared__ int sh_last;

    int b   = blockIdx.x >> 8;         // batch row
    int cb  = blockIdx.x & 255;        // chunk within row
    int t0  = cb * ROWS_PER_BLK;
    int tid = threadIdx.x;
    int lane = tid & 31;

    // --- per-row length scan (warp 0, two 32-chunks) ---
    if (tid < 32) {
        int carry = 0;
#pragma unroll
        for (int c = 0; c < 2; c++) {
            int idx = c * 32 + lane;
            int v = lengths[b * N_ + idx];
            int s = v;
#pragma unroll
            for (int o = 1; o < 32; o <<= 1) {
                int t = __shfl_up_sync(0xffffffffu, s, o);
                if (lane >= o) s += t;
            }
            sh_off[idx] = carry + (s - v);
            carry += __shfl_sync(0xffffffffu, s, 31);
        }
        if (lane == 0) sh_off[N_] = carry;
    }
    __syncthreads();

    int ltot = sh_off[N_];
    if (cb == 0 && tid == 0)
        out[OFF_LEN + b] = (float)ltot;

    // --- row -> (node, pos) mapping for this block's 32 rows ---
    if (tid < ROWS_PER_BLK) {
        int t = t0 + tid;
        int m = -1;
        if (t < ltot) {
            int lo = 0, hi = 63;
#pragma unroll
            for (int it = 0; it < 6; it++) {
                int mid = (lo + hi + 1) >> 1;
                if (sh_off[mid] <= t) lo = mid; else hi = mid - 1;
            }
            m = (lo << 8) | (t - sh_off[lo]);
        }
        sh_map[tid] = m;
    }
    __syncthreads();

    float*  out_src = out;
    float4* out_mb  = (float4*)(out + OFF_MB);

    int ps = tid >> 6;            // 0..3 row sub-index
    int dt = tid & 63;            // float4 lane within a D=256 row

    const float4 z4 = make_float4(0.f, 0.f, 0.f, 0.f);
    float4 acc = z4;

    // --- 2 outer iters x 4 rows in flight per thread (MLP=4) ---
#pragma unroll
    for (int k0 = 0; k0 < ROWS_PER_BLK; k0 += 16) {
        int kA = k0 + ps, kB = kA + 4, kC = kA + 8, kD = kA + 12;
        int mA = sh_map[kA], mB = sh_map[kB], mC = sh_map[kC], mD = sh_map[kD];
        float4 vA = z4, vB = z4, vC = z4, vD = z4;
        float  sA = 1.f, sB = 1.f, sC = 1.f, sD = 1.f;
        if (mA >= 0) vA = __ldcs(&mb[((size_t)(mA & 255) * NB_ + (b << 6) + (mA >> 8)) * (D_ / 4) + dt]);
        if (mB >= 0) vB = __ldcs(&mb[((size_t)(mB & 255) * NB_ + (b << 6) + (mB >> 8)) * (D_ / 4) + dt]);
        if (mC >= 0) vC = __ldcs(&mb[((size_t)(mC & 255) * NB_ + (b << 6) + (mC >> 8)) * (D_ / 4) + dt]);
        if (mD >= 0) vD = __ldcs(&mb[((size_t)(mD & 255) * NB_ + (b << 6) + (mD >> 8)) * (D_ / 4) + dt]);
        if (dt == 0) {
            if (mA >= 0) sA = src[(size_t)(mA & 255) * NB_ + __ldg(&recover[(b << 6) + (mA >> 8)])];
            if (mB >= 0) sB = src[(size_t)(mB & 255) * NB_ + __ldg(&recover[(b << 6) + (mB >> 8)])];
            if (mC >= 0) sC = src[(size_t)(mC & 255) * NB_ + __ldg(&recover[(b << 6) + (mC >> 8)])];
            if (mD >= 0) sD = src[(size_t)(mD & 255) * NB_ + __ldg(&recover[(b << 6) + (mD >> 8)])];
        }
        acc.x += (vA.x + vB.x) + (vC.x + vD.x);
        acc.y += (vA.y + vB.y) + (vC.y + vD.y);
        acc.z += (vA.z + vB.z) + (vC.z + vD.z);
        acc.w += (vA.w + vB.w) + (vC.w + vD.w);
        int tA = t0 + kA, tB = t0 + kB, tC = t0 + kC, tD = t0 + kD;
        __stcs(&out_mb[((size_t)tA * B_ + b) * (D_ / 4) + dt], vA);
        __stcs(&out_mb[((size_t)tB * B_ + b) * (D_ / 4) + dt], vB);
        __stcs(&out_mb[((size_t)tC * B_ + b) * (D_ / 4) + dt], vC);
        __stcs(&out_mb[((size_t)tD * B_ + b) * (D_ / 4) + dt], vD);
        if (dt == 0) {
            out_src[(size_t)tA * B_ + b] = sA;
            out_src[(size_t)tB * B_ + b] = sB;
            out_src[(size_t)tC * B_ + b] = sC;
            out_src[(size_t)tD * B_ + b] = sD;
        }
    }

    // --- block-reduce the mean-pool partial, atomicAdd into g_hid ---
    sh[tid] = acc;
    __syncthreads();
    if (ps == 0) {
        float4 a0 = sh[dt], a1 = sh[64 + dt], a2 = sh[128 + dt], a3 = sh[192 + dt];
        float* h = g_hid + b * D_ + dt * 4;
        atomicAdd(h + 0, a0.x + a1.x + a2.x + a3.x);
        atomicAdd(h + 1, a0.y + a1.y + a2.y + a3.y);
        atomicAdd(h + 2, a0.z + a1.z + a2.z + a3.z);
        atomicAdd(h + 3, a0.w + a1.w + a2.w + a3.w);
    }
    __threadfence();
    __syncthreads();

    if (tid == 0)
        sh_last = (atomicAdd(&g_cnt[b], 1) == BLKS_PER_B - 1);
    __syncthreads();

    // --- last block of this batch row: finalize hidden, restore scratch ---
    if (sh_last) {
        __threadfence();
        float inv = ltot > 0 ? 1.0f / (float)ltot : 0.0f;
        float v = g_hid[b * D_ + tid];
        out[OFF_HID + (size_t)b * D_ + tid] = v * inv;
        g_hid[b * D_ + tid] = 0.0f;     // restore for next graph replay
        __syncthreads();
        if (tid == 0)
            g_cnt[b] = 0;
    }
}

// ---------------------------------------------------------------------------
extern "C" void kernel_launch(void* const* d_in, const int* in_sizes, int n_in,
                              void* d_out, int out_size) {
    const float* src     = (const float*)d_in[0];   // [L, NB, 1]
    const float* mb      = (const float*)d_in[1];   // [L, NB, D]
    const int*   lengths = (const int*)d_in[2];     // [NB]
    const int*   recover = (const int*)d_in[3];     // [NB]
    float* out = (float*)d_out;

    fused_kernel<<<GRID_, 256>>>(src, (const float4*)mb, lengths, recover, out);
}

// round 13
// speedup vs baseline: 1.7341x; 1.7341x over previous
#include <cuda_runtime.h>

// Fixed problem shape (from setup_inputs): B=32, N=64, L=128, D=256
#define B_      32
#define N_      64
#define L_      128
#define D_      256
#define NB_     (B_ * N_)     // 2048
#define MAXLEN_ (N_ * L_)     // 8192

// Output layout (flat concat of the reference tuple, fp32):
//   src_out      [MAXLEN, B, 1]
//   mb_out       [MAXLEN, B, D]
//   hidden       [1, B, D]
//   lengths_out  [B]
#define OFF_MB      ((size_t)MAXLEN_ * B_)
#define OFF_HID     (OFF_MB + (size_t)MAXLEN_ * B_ * D_)
#define OFF_LEN     (OFF_HID + (size_t)B_ * D_)

// Per-block mean-pool partials + arrival counters. Zero at module load; the
// last block per batch row resets them after use so every graph replay sees
// identical initial state.
__device__ float4 g_part[NB_ * (D_ / 4)];   // [2048][64] float4 = 2 MB
__device__ int    g_cnt[B_];

// ---------------------------------------------------------------------------
// Fused scatter kernel (one block per node), R8 logic with ONE change:
// block index mapping is b = blockIdx&31, n = blockIdx>>5, so co-resident
// blocks span ALL batch rows at the same node range (dense DRAM footprint
// on both the read slabs and the write rows).
// ---------------------------------------------------------------------------
__global__ void __launch_bounds__(256) fused_kernel(
        const float* __restrict__ src,
        const float4* __restrict__ mb,
        const int* __restrict__ lengths,
        const int* __restrict__ recover,
        float* __restrict__ out) {
    __shared__ int sh_off[N_ + 1];
    __shared__ float4 sh[256];
    __shared__ int sh_last;

    int b   = blockIdx.x & 31;    // batch row   (swapped mapping)
    int n   = blockIdx.x >> 5;    // node within row
    int nb  = (b << 6) | n;
    int tid = threadIdx.x;
    int lane = tid & 31;

    // --- per-row length scan (warp 0, two 32-chunks) ---
    if (tid < 32) {
        int carry = 0;
#pragma unroll
        for (int c = 0; c < 2; c++) {
            int idx = c * 32 + lane;
            int v = lengths[b * N_ + idx];
            int s = v;
#pragma unroll
            for (int o = 1; o < 32; o <<= 1) {
                int t = __shfl_up_sync(0xffffffffu, s, o);
                if (lane >= o) s += t;
            }
            sh_off[idx] = carry + (s - v);
            carry += __shfl_sync(0xffffffffu, s, 31);
        }
        if (lane == 0) sh_off[N_] = carry;
    }
    __syncthreads();

    int len  = lengths[nb];
    int off  = sh_off[n];
    int ltot = sh_off[N_];
    int rec  = recover[nb];

    if (n == 0 && tid == 0)
        out[OFF_LEN + b] = (float)ltot;

    float*  out_src = out;
    float4* out_mb  = (float4*)(out + OFF_MB);

    int ps = tid >> 6;            // 0..3 position sub-index
    int dt = tid & 63;            // float4 lane within a D=256 row

    const float4 z4 = make_float4(0.f, 0.f, 0.f, 0.f);
    float4 acc = z4;

    // --- valid-region stream, 4 rows in flight per thread ---
    int p0 = 0;
    for (; p0 + 16 <= len; p0 += 16) {
        int pA = p0 + ps, pB = pA + 4, pC = pA + 8, pD = pA + 12;
        float4 vA = __ldcs(&mb[((size_t)pA * NB_ + nb) * (D_ / 4) + dt]);
        float4 vB = __ldcs(&mb[((size_t)pB * NB_ + nb) * (D_ / 4) + dt]);
        float4 vC = __ldcs(&mb[((size_t)pC * NB_ + nb) * (D_ / 4) + dt]);
        float4 vD = __ldcs(&mb[((size_t)pD * NB_ + nb) * (D_ / 4) + dt]);
        float sA = 0.f, sB = 0.f, sC = 0.f, sD = 0.f;
        if (dt == 0) {
            sA = src[(size_t)pA * NB_ + rec];
            sB = src[(size_t)pB * NB_ + rec];
            sC = src[(size_t)pC * NB_ + rec];
            sD = src[(size_t)pD * NB_ + rec];
        }
        acc.x += (vA.x + vB.x) + (vC.x + vD.x);
        acc.y += (vA.y + vB.y) + (vC.y + vD.y);
        acc.z += (vA.z + vB.z) + (vC.z + vD.z);
        acc.w += (vA.w + vB.w) + (vC.w + vD.w);
        int tA = off + pA, tB = off + pB, tC = off + pC, tD = off + pD;
        __stcs(&out_mb[((size_t)tA * B_ + b) * (D_ / 4) + dt], vA);
        __stcs(&out_mb[((size_t)tB * B_ + b) * (D_ / 4) + dt], vB);
        __stcs(&out_mb[((size_t)tC * B_ + b) * (D_ / 4) + dt], vC);
        __stcs(&out_mb[((size_t)tD * B_ + b) * (D_ / 4) + dt], vD);
        if (dt == 0) {
            out_src[(size_t)tA * B_ + b] = sA;
            out_src[(size_t)tB * B_ + b] = sB;
            out_src[(size_t)tC * B_ + b] = sC;
            out_src[(size_t)tD * B_ + b] = sD;
        }
    }
    for (; p0 < len; p0 += 4) {
        int pos = p0 + ps;
        if (pos < len) {
            float4 v = __ldcs(&mb[((size_t)pos * NB_ + nb) * (D_ / 4) + dt]);
            acc.x += v.x; acc.y += v.y; acc.z += v.z; acc.w += v.w;
            int t = off + pos;
            __stcs(&out_mb[((size_t)t * B_ + b) * (D_ / 4) + dt], v);
            if (dt == 0)
                out_src[(size_t)t * B_ + b] = src[(size_t)pos * NB_ + rec];
        }
    }

    // --- balanced tail: exactly (128 - len) rows, exact partition ---
    int t0 = ltot + 128 * n - off;
    int t1 = t0 + (128 - len);
    for (int tb = t0; tb < t1; tb += 4) {
        int t = tb + ps;
        if (t < t1) {
            __stcs(&out_mb[((size_t)t * B_ + b) * (D_ / 4) + dt], z4);
            if (dt == 0)
                out_src[(size_t)t * B_ + b] = 1.0f;
        }
    }

    // --- publish mean-pool partial ---
    sh[tid] = acc;
    __syncthreads();
    if (ps == 0) {
        float4 a0 = sh[dt], a1 = sh[64 + dt], a2 = sh[128 + dt], a3 = sh[192 + dt];
        float4 r;
        r.x = a0.x + a1.x + a2.x + a3.x;
        r.y = a0.y + a1.y + a2.y + a3.y;
        r.z = a0.z + a1.z + a2.z + a3.z;
        r.w = a0.w + a1.w + a2.w + a3.w;
        g_part[(size_t)nb * (D_ / 4) + dt] = r;
    }
    __threadfence();
    __syncthreads();

    if (tid == 0)
        sh_last = (atomicAdd(&g_cnt[b], 1) == 63);
    __syncthreads();

    // --- last block of this batch row: reduce 64 partials -> hidden ---
    if (sh_last) {
        int col = tid & 63, q = tid >> 6;
        float4 s = z4;
#pragma unroll
        for (int j = 0; j < 16; j++) {
            int cb = q * 16 + j;
            float4 v = __ldcg(&g_part[(size_t)(b * 64 + cb) * (D_ / 4) + col]);
            s.x += v.x; s.y += v.y; s.z += v.z; s.w += v.w;
        }
        sh[tid] = s;
        __syncthreads();
        if (ps == 0) {
            float4 a0 = sh[dt], a1 = sh[64 + dt], a2 = sh[128 + dt], a3 = sh[192 + dt];
            float inv = ltot > 0 ? 1.0f / (float)ltot : 0.0f;
            float4 r;
            r.x = (a0.x + a1.x + a2.x + a3.x) * inv;
            r.y = (a0.y + a1.y + a2.y + a3.y) * inv;
            r.z = (a0.z + a1.z + a2.z + a3.z) * inv;
            r.w = (a0.w + a1.w + a2.w + a3.w) * inv;
            ((float4*)(out + OFF_HID))[b * (D_ / 4) + dt] = r;
        }
        if (tid == 0)
            g_cnt[b] = 0;        // restore for next graph replay
    }
}

// ---------------------------------------------------------------------------
extern "C" void kernel_launch(void* const* d_in, const int* in_sizes, int n_in,
                              void* d_out, int out_size) {
    const float* src     = (const float*)d_in[0];   // [L, NB, 1]
    const float* mb      = (const float*)d_in[1];   // [L, NB, D]
    const int*   lengths = (const int*)d_in[2];     // [NB]
    const int*   recover = (const int*)d_in[3];     // [NB]
    float* out = (float*)d_out;

    fused_kernel<<<NB_, 256>>>(src, (const float4*)mb, lengths, recover, out);
}